// round 7
// baseline (speedup 1.0000x reference)
#include <cuda_runtime.h>
#include <cuda_bf16.h>
#include <cstdint>

#define NB   64
#define NS   6
#define NT   2000
#define NC   25
#define BLOCK        256
#define TILE_ROWS    256
#define TILES_PER_S  500                   // 128000/256
#define NTILES       (NS * TILES_PER_S)    // 3000
#define GRID         296                   // 148 SMs x 2 blocks
#define STAGES       4
#define PLANE        (NT * NC)             // 50000
#define BSTRIDE      (NS * NT * NC)        // 300000
#define COLS         (NS * NT)             // 12000
#define TILE_FLOATS  (TILE_ROWS * NC)      // 6400
#define TILE_F4      (TILE_FLOATS / 4)     // 1600
#define TILE_BYTES   (TILE_FLOATS * 4)     // 25600
#define RING_BYTES   (STAGES * TILE_BYTES) // 102400
#define OC           48                    // onset cols/block; 250 blocks cover 12000

__device__ float g_fret_part[NTILES];
__device__ float g_onset_st[COLS];
__device__ int   g_count;                  // zero-initialized; reset by last block

__device__ __forceinline__ uint32_t s2u(const void* p) {
    uint32_t a;
    asm("{ .reg .u64 t; cvta.to.shared.u64 t, %1; cvt.u32.u64 %0, t; }"
        : "=r"(a) : "l"(p));
    return a;
}
__device__ __forceinline__ void cp16(uint32_t dst, const void* src) {
    asm volatile("cp.async.cg.shared.global [%0], [%1], 16;\n"
                 :: "r"(dst), "l"(src));
}

// Stage one 256-row tile (global tile id g) into smem, then commit a group.
__device__ __forceinline__ void stage_tile(const float* __restrict__ of,
                                           int g, uint32_t sbase) {
    const int s  = g / TILES_PER_S;
    const int lt = g - s * TILES_PER_S;
    const int p0 = lt * TILE_FLOATS;         // float offset within s-plane
    #pragma unroll
    for (int j = 0; j < 7; j++) {
        int q = threadIdx.x + j * BLOCK;     // float4 index in tile
        if (q < TILE_F4) {
            int p = p0 + q * 4;
            int b = p / PLANE;               // constant across the float4
            const float* src = of + (p + b * (BSTRIDE - PLANE) + s * PLANE);
            cp16(sbase + q * 16, src);
        }
    }
    asm volatile("cp.async.commit_group;\n");
}

extern __shared__ float ring[];              // STAGES * TILE_FLOATS floats

__global__ __launch_bounds__(BLOCK) void fused_kernel(
    const float* __restrict__ of,    // [B,S,T,C]
    const int*   __restrict__ tf,    // [B,S,T]
    const float* __restrict__ oo,    // [B,S,T]
    const float* __restrict__ to,    // [B,S,T]
    float* __restrict__ out, int out_size)
{
    __shared__ float wred[BLOCK / 32];
    __shared__ int   s_last;

    const int bid = blockIdx.x;
    // tile partition: blocks 0..39 take 11 tiles, 40..295 take 10 (40*11+256*10=3000)
    int t0, ntile;
    if (bid < 40) { t0 = bid * 11;            ntile = 11; }
    else          { t0 = 440 + (bid - 40) * 10; ntile = 10; }

    const uint32_t sb = s2u(ring);

    // ---------------- fret CE: 4-stage cp.async ring ----------------
    #pragma unroll
    for (int i = 0; i < STAGES; i++)          // ntile >= 10 > STAGES always
        stage_tile(of, t0 + i, sb + (i & 3) * TILE_BYTES);

    for (int i = 0; i < ntile; i++) {
        const int g   = t0 + i;
        const int s   = g / TILES_PER_S;
        const int row = (g - s * TILES_PER_S) * TILE_ROWS + threadIdx.x;
        const int b   = row / NT;
        const int t   = row - b * NT;
        const int tgt = tf[(b * NS + s) * NT + t];   // LDG before the wait

        asm volatile("cp.async.wait_group %0;\n" :: "n"(STAGES - 1) : "memory");
        __syncthreads();

        const float* x = ring + (i & 3) * TILE_FLOATS + threadIdx.x * NC;

        float v[NC];
        #pragma unroll
        for (int c = 0; c < NC; c++) v[c] = x[c];

        float m = v[0];
        #pragma unroll
        for (int c = 1; c < NC; c++) m = fmaxf(m, v[c]);

        float sum = 0.f;
        #pragma unroll
        for (int c = 0; c < NC; c++) sum += __expf(v[c] - m);

        float nll = __logf(sum) + m - x[tgt];

        #pragma unroll
        for (int o = 16; o > 0; o >>= 1)
            nll += __shfl_down_sync(0xFFFFFFFFu, nll, o);
        const int wid = threadIdx.x >> 5;
        const int lid = threadIdx.x & 31;
        if (lid == 0) wred[wid] = nll;
        __syncthreads();                      // ring slot free + wred ready
        if (threadIdx.x == 0) {
            float a = 0.f;
            #pragma unroll
            for (int w = 0; w < BLOCK / 32; w++) a += wred[w];
            g_fret_part[g] = a;
        }
        // refill the slot just consumed (or keep group count constant)
        if (i + STAGES < ntile)
            stage_tile(of, t0 + i + STAGES, sb + (i & 3) * TILE_BYTES);
        else
            asm volatile("cp.async.commit_group;\n");
    }
    asm volatile("cp.async.wait_group 0;\n" ::: "memory");
    __syncthreads();

    // ---------------- onset: blocks 40..289 take 48 columns each ----------------
    if (bid >= 40 && bid < 290) {
        float* so  = ring;                    // 64x48
        float* st_ = ring + NB * OC;
        const int col0 = (bid - 40) * OC;

        for (int i = threadIdx.x; i < NB * OC; i += BLOCK) {
            int b = i / OC, c = i - b * OC;
            int gidx = b * COLS + col0 + c;
            so[i]  = oo[gidx];
            st_[i] = to[gidx];
        }
        __syncthreads();

        if (threadIdx.x < 4 * OC) {
            const int c = threadIdx.x >> 2;   // column 0..47
            const int q = threadIdx.x & 3;    // batch quarter

            float m = -3.402823466e+38f;
            #pragma unroll
            for (int i = 0; i < 16; i++)
                m = fmaxf(m, so[(q * 16 + i) * OC + c]);
            m = fmaxf(m, __shfl_xor_sync(0xFFFFFFFFu, m, 1));
            m = fmaxf(m, __shfl_xor_sync(0xFFFFFFFFu, m, 2));

            float sum = 0.f, ts = 0.f, txs = 0.f;
            #pragma unroll
            for (int i = 0; i < 16; i++) {
                float xv = so [(q * 16 + i) * OC + c];
                float tg = st_[(q * 16 + i) * OC + c];
                sum += __expf(xv - m);
                ts  += tg;
                txs += tg * xv;
            }
            sum += __shfl_xor_sync(0xFFFFFFFFu, sum, 1);
            sum += __shfl_xor_sync(0xFFFFFFFFu, sum, 2);
            ts  += __shfl_xor_sync(0xFFFFFFFFu, ts, 1);
            ts  += __shfl_xor_sync(0xFFFFFFFFu, ts, 2);
            txs += __shfl_xor_sync(0xFFFFFFFFu, txs, 1);
            txs += __shfl_xor_sync(0xFFFFFFFFu, txs, 2);

            if (q == 0)
                g_onset_st[col0 + c] = (__logf(sum) + m) * ts - txs;
        }
    }

    // ---------------- last block does the final deterministic reduction ----------------
    __threadfence();
    __syncthreads();
    if (threadIdx.x == 0)
        s_last = (atomicAdd(&g_count, 1) == GRID - 1) ? 1 : 0;
    __syncthreads();
    if (!s_last) return;

    __threadfence();                          // acquire side
    if (threadIdx.x == 0) g_count = 0;        // reset for next graph replay

    __shared__ float fs[NS], os_[NS];
    const int w   = threadIdx.x >> 5;
    const int lid = threadIdx.x & 31;

    if (w < NS) {
        float a = 0.f;
        for (int i = lid; i < TILES_PER_S; i += 32)
            a += g_fret_part[w * TILES_PER_S + i];
        #pragma unroll
        for (int o = 16; o > 0; o >>= 1)
            a += __shfl_down_sync(0xFFFFFFFFu, a, o);

        float b = 0.f;
        for (int i = lid; i < NT; i += 32)
            b += g_onset_st[w * NT + i];
        #pragma unroll
        for (int o = 16; o > 0; o >>= 1)
            b += __shfl_down_sync(0xFFFFFFFFu, b, o);

        if (lid == 0) {
            fs[w]  = a * (1.0f / NB);         // mean over batch
            os_[w] = b;
        }
    }
    __syncthreads();

    if (threadIdx.x == 0) {
        float fl = 0.f, ol = 0.f;
        #pragma unroll
        for (int s = 0; s < NS; s++) { fl += fs[s]; ol += os_[s]; }
        float loss = 0.5f * fl + 0.5f * ol;
        if (0 < out_size) out[0] = loss;
        if (1 < out_size) out[1] = fl;
        if (2 < out_size) out[2] = ol;
        #pragma unroll
        for (int s = 0; s < NS; s++) {
            if (3 + s < out_size) out[3 + s] = fs[s];
            if (9 + s < out_size) out[9 + s] = os_[s];
        }
    }
    for (int i = 15 + (int)threadIdx.x; i < out_size; i += (int)blockDim.x)
        out[i] = 0.f;
}

extern "C" void kernel_launch(void* const* d_in, const int* in_sizes, int n_in,
                              void* d_out, int out_size) {
    const float* output_fret  = (const float*)d_in[0];
    const int*   target_fret  = (const int*)  d_in[1];
    const float* output_onset = (const float*)d_in[2];
    const float* target_onset = (const float*)d_in[3];
    float* out = (float*)d_out;

    cudaFuncSetAttribute(fused_kernel,
                         cudaFuncAttributeMaxDynamicSharedMemorySize,
                         RING_BYTES);

    fused_kernel<<<GRID, BLOCK, RING_BYTES>>>(
        output_fret, target_fret, output_onset, target_onset, out, out_size);
}

// round 8
// speedup vs baseline: 1.3635x; 1.3635x over previous
#include <cuda_runtime.h>
#include <cuda_bf16.h>
#include <cstdint>

#define NB   64
#define NS   6
#define NT   2000
#define NC   25
#define BLOCK        256
#define TILE_ROWS    256
#define TILES_PER_S  500                   // 128000/256
#define TPB          4                     // tiles per fret block (same s)
#define BLKS_PER_S   (TILES_PER_S / TPB)   // 125
#define FRET_BLKS    (NS * BLKS_PER_S)     // 750
#define ONSET_BLKS   250
#define GRID         (FRET_BLKS + ONSET_BLKS)  // 1000
#define STAGES       2
#define PLANE        (NT * NC)             // 50000
#define BSTRIDE      (NS * NT * NC)        // 300000
#define COLS         (NS * NT)             // 12000
#define TILE_FLOATS  (TILE_ROWS * NC)      // 6400
#define TILE_F4      (TILE_FLOATS / 4)     // 1600
#define TILE_BYTES   (TILE_FLOATS * 4)     // 25600
#define RING_BYTES   (STAGES * TILE_BYTES) // 51200
#define OC           48                    // onset cols per onset block

__device__ float g_fret_part[FRET_BLKS];   // per-block partial, grouped by s
__device__ float g_onset_st[COLS];

__device__ __forceinline__ uint32_t s2u(const void* p) {
    uint32_t a;
    asm("{ .reg .u64 t; cvta.to.shared.u64 t, %1; cvt.u32.u64 %0, t; }"
        : "=r"(a) : "l"(p));
    return a;
}
__device__ __forceinline__ void cp16(uint32_t dst, const void* src) {
    asm volatile("cp.async.cg.shared.global [%0], [%1], 16;\n"
                 :: "r"(dst), "l"(src));
}

// Stage one 256-row tile: string s, local tile lt (0..499) -> smem slot.
__device__ __forceinline__ void stage_tile(const float* __restrict__ of,
                                           int s, int lt, uint32_t sbase) {
    const int p0 = lt * TILE_FLOATS;         // float offset within the s-plane
    #pragma unroll
    for (int j = 0; j < 7; j++) {
        int q = threadIdx.x + j * BLOCK;     // float4 index in tile
        if (q < TILE_F4) {
            int p = p0 + q * 4;
            int b = p / PLANE;               // constant across the float4
            const float* src = of + (p + b * (BSTRIDE - PLANE) + s * PLANE);
            cp16(sbase + q * 16, src);
        }
    }
    asm volatile("cp.async.commit_group;\n");
}

extern __shared__ float ring[];              // STAGES * TILE_FLOATS floats

__global__ __launch_bounds__(BLOCK) void fused_kernel(
    const float* __restrict__ of,    // [B,S,T,C]
    const int*   __restrict__ tf,    // [B,S,T]
    const float* __restrict__ oo,    // [B,S,T]
    const float* __restrict__ to)    // [B,S,T]
{
    const int bid = blockIdx.x;

    if (bid < FRET_BLKS) {
        // ======================= fret CE =======================
        __shared__ float wred[BLOCK / 32];
        const int s   = bid / BLKS_PER_S;
        const int blk = bid - s * BLKS_PER_S;
        const int lt0 = blk * TPB;           // first local tile (0..499)
        const uint32_t sb = s2u(ring);

        stage_tile(of, s, lt0 + 0, sb);
        stage_tile(of, s, lt0 + 1, sb + TILE_BYTES);

        float acc = 0.f;                     // per-thread NLL accumulator

        #pragma unroll
        for (int i = 0; i < TPB; i++) {
            const int row = (lt0 + i) * TILE_ROWS + threadIdx.x;
            const int b   = row / NT;
            const int t   = row - b * NT;
            const int tgt = tf[(b * NS + s) * NT + t];  // LDG before the wait

            asm volatile("cp.async.wait_group %0;\n" :: "n"(STAGES - 1) : "memory");
            __syncthreads();

            const float* x = ring + (i & 1) * TILE_FLOATS + threadIdx.x * NC;

            float v[NC];
            #pragma unroll
            for (int c = 0; c < NC; c++) v[c] = x[c];
            const float xt = x[tgt];

            __syncthreads();                 // slot fully read -> refill ok
            if (i + STAGES < TPB)
                stage_tile(of, s, lt0 + i + STAGES, sb + (i & 1) * TILE_BYTES);
            else
                asm volatile("cp.async.commit_group;\n");

            float m = v[0];
            #pragma unroll
            for (int c = 1; c < NC; c++) m = fmaxf(m, v[c]);

            float sum = 0.f;
            #pragma unroll
            for (int c = 0; c < NC; c++) sum += __expf(v[c] - m);

            acc += __logf(sum) + m - xt;
        }
        asm volatile("cp.async.wait_group 0;\n" ::: "memory");

        // single block reduction at the end
        #pragma unroll
        for (int o = 16; o > 0; o >>= 1)
            acc += __shfl_down_sync(0xFFFFFFFFu, acc, o);
        const int wid = threadIdx.x >> 5;
        const int lid = threadIdx.x & 31;
        if (lid == 0) wred[wid] = acc;
        __syncthreads();
        if (threadIdx.x == 0) {
            float a = 0.f;
            #pragma unroll
            for (int w = 0; w < BLOCK / 32; w++) a += wred[w];
            g_fret_part[bid] = a;
        }
    } else {
        // ======================= onset (softmax over batch) =======================
        float* so  = ring;                   // [64 x 48]
        float* st_ = ring + NB * OC;
        const int col0 = (bid - FRET_BLKS) * OC;

        for (int i = threadIdx.x; i < NB * OC; i += BLOCK) {
            int b = i / OC, c = i - b * OC;
            int gidx = b * COLS + col0 + c;
            so[i]  = oo[gidx];
            st_[i] = to[gidx];
        }
        __syncthreads();

        if (threadIdx.x < 4 * OC) {
            const int c = threadIdx.x >> 2;  // column 0..47
            const int q = threadIdx.x & 3;   // batch quarter

            float m = -3.402823466e+38f;
            #pragma unroll
            for (int i = 0; i < 16; i++)
                m = fmaxf(m, so[(q * 16 + i) * OC + c]);
            m = fmaxf(m, __shfl_xor_sync(0xFFFFFFFFu, m, 1));
            m = fmaxf(m, __shfl_xor_sync(0xFFFFFFFFu, m, 2));

            float sum = 0.f, ts = 0.f, txs = 0.f;
            #pragma unroll
            for (int i = 0; i < 16; i++) {
                float xv = so [(q * 16 + i) * OC + c];
                float tg = st_[(q * 16 + i) * OC + c];
                sum += __expf(xv - m);
                ts  += tg;
                txs += tg * xv;
            }
            sum += __shfl_xor_sync(0xFFFFFFFFu, sum, 1);
            sum += __shfl_xor_sync(0xFFFFFFFFu, sum, 2);
            ts  += __shfl_xor_sync(0xFFFFFFFFu, ts, 1);
            ts  += __shfl_xor_sync(0xFFFFFFFFu, ts, 2);
            txs += __shfl_xor_sync(0xFFFFFFFFu, txs, 1);
            txs += __shfl_xor_sync(0xFFFFFFFFu, txs, 2);

            if (q == 0)
                g_onset_st[col0 + c] = (__logf(sum) + m) * ts - txs;
        }
    }
}

// ---------------------------------------------------------------------------
// Final deterministic reduction. Output (15 fp32): loss, fret_loss,
// onset_loss, fret_string[6], onset_string[6].
// ---------------------------------------------------------------------------
__global__ void final_kernel(float* __restrict__ out, int out_size)
{
    __shared__ float fs[NS], os_[NS];
    const int w   = threadIdx.x >> 5;
    const int lid = threadIdx.x & 31;

    if (w < NS) {
        float a = 0.f;
        for (int i = lid; i < BLKS_PER_S; i += 32)
            a += g_fret_part[w * BLKS_PER_S + i];
        #pragma unroll
        for (int o = 16; o > 0; o >>= 1)
            a += __shfl_down_sync(0xFFFFFFFFu, a, o);

        float b = 0.f;
        for (int i = lid; i < NT; i += 32)
            b += g_onset_st[w * NT + i];
        #pragma unroll
        for (int o = 16; o > 0; o >>= 1)
            b += __shfl_down_sync(0xFFFFFFFFu, b, o);

        if (lid == 0) {
            fs[w]  = a * (1.0f / NB);        // mean over batch
            os_[w] = b;
        }
    }
    __syncthreads();

    if (threadIdx.x == 0) {
        float fl = 0.f, ol = 0.f;
        #pragma unroll
        for (int s = 0; s < NS; s++) { fl += fs[s]; ol += os_[s]; }
        float loss = 0.5f * fl + 0.5f * ol;
        if (0 < out_size) out[0] = loss;
        if (1 < out_size) out[1] = fl;
        if (2 < out_size) out[2] = ol;
        #pragma unroll
        for (int s = 0; s < NS; s++) {
            if (3 + s < out_size) out[3 + s] = fs[s];
            if (9 + s < out_size) out[9 + s] = os_[s];
        }
    }
    for (int i = 15 + (int)threadIdx.x; i < out_size; i += (int)blockDim.x)
        out[i] = 0.f;
}

extern "C" void kernel_launch(void* const* d_in, const int* in_sizes, int n_in,
                              void* d_out, int out_size) {
    const float* output_fret  = (const float*)d_in[0];
    const int*   target_fret  = (const int*)  d_in[1];
    const float* output_onset = (const float*)d_in[2];
    const float* target_onset = (const float*)d_in[3];
    float* out = (float*)d_out;

    cudaFuncSetAttribute(fused_kernel,
                         cudaFuncAttributeMaxDynamicSharedMemorySize,
                         RING_BYTES);

    fused_kernel<<<GRID, BLOCK, RING_BYTES>>>(
        output_fret, target_fret, output_onset, target_onset);
    final_kernel<<<1, 192>>>(out, out_size);
}

// round 12
// speedup vs baseline: 1.6067x; 1.1783x over previous
#include <cuda_runtime.h>
#include <cuda_bf16.h>
#include <cstdint>

#define NB   64
#define NS   6
#define NT   2000
#define NC   25
#define BLOCK        256
#define TILE_ROWS    256
#define TILES_PER_S  500                   // 128000/256
#define TPB          4                     // tiles per fret block (same s)
#define BLKS_PER_S   (TILES_PER_S / TPB)   // 125
#define FRET_BLKS    (NS * BLKS_PER_S)     // 750
#define OC           40                    // onset cols per block; 4*OC=160 = 5 full warps
#define OBLKS_PER_S  (NT / OC)             // 50
#define ONSET_BLKS   (NS * OBLKS_PER_S)    // 300
#define GRID         (FRET_BLKS + ONSET_BLKS)  // 1050
#define STAGES       2
#define PLANE        (NT * NC)             // 50000
#define BSTRIDE      (NS * NT * NC)        // 300000
#define COLS         (NS * NT)             // 12000
#define TILE_FLOATS  (TILE_ROWS * NC)      // 6400
#define TILE_F4      (TILE_FLOATS / 4)     // 1600
#define TILE_BYTES   (TILE_FLOATS * 4)     // 25600
#define RING_BYTES   (STAGES * TILE_BYTES) // 51200

__device__ float g_fret_part[FRET_BLKS];   // per-block partial, grouped by s
__device__ float g_onset_part[ONSET_BLKS]; // per-block partial, grouped by s

__device__ __forceinline__ uint32_t s2u(const void* p) {
    uint32_t a;
    asm("{ .reg .u64 t; cvta.to.shared.u64 t, %1; cvt.u32.u64 %0, t; }"
        : "=r"(a) : "l"(p));
    return a;
}
__device__ __forceinline__ void cp16(uint32_t dst, const void* src) {
    asm volatile("cp.async.cg.shared.global [%0], [%1], 16;\n"
                 :: "r"(dst), "l"(src));
}

// Stage one 256-row tile: string s, local tile lt (0..499) -> smem slot.
__device__ __forceinline__ void stage_tile(const float* __restrict__ of,
                                           int s, int lt, uint32_t sbase) {
    const int p0 = lt * TILE_FLOATS;         // float offset within the s-plane
    #pragma unroll
    for (int j = 0; j < 7; j++) {
        int q = threadIdx.x + j * BLOCK;     // float4 index in tile
        if (q < TILE_F4) {
            int p = p0 + q * 4;
            int b = p / PLANE;               // constant across the float4
            const float* src = of + (p + b * (BSTRIDE - PLANE) + s * PLANE);
            cp16(sbase + q * 16, src);
        }
    }
    asm volatile("cp.async.commit_group;\n");
}

extern __shared__ float ring[];              // STAGES * TILE_FLOATS floats

__global__ __launch_bounds__(BLOCK) void fused_kernel(
    const float* __restrict__ of,    // [B,S,T,C]
    const int*   __restrict__ tf,    // [B,S,T]
    const float* __restrict__ oo,    // [B,S,T]
    const float* __restrict__ to)    // [B,S,T]
{
    const int bid = blockIdx.x;

    if (bid < FRET_BLKS) {
        // ======================= fret CE =======================
        __shared__ float wred[BLOCK / 32];
        const int s   = bid / BLKS_PER_S;
        const int blk = bid - s * BLKS_PER_S;
        const int lt0 = blk * TPB;           // first local tile (0..499)
        const uint32_t sb = s2u(ring);

        stage_tile(of, s, lt0 + 0, sb);
        stage_tile(of, s, lt0 + 1, sb + TILE_BYTES);

        float acc = 0.f;                     // per-thread NLL accumulator

        #pragma unroll
        for (int i = 0; i < TPB; i++) {
            const int row = (lt0 + i) * TILE_ROWS + threadIdx.x;
            const int b   = row / NT;
            const int t   = row - b * NT;
            const int tgt = tf[(b * NS + s) * NT + t];  // LDG before the wait

            asm volatile("cp.async.wait_group %0;\n" :: "n"(STAGES - 1) : "memory");
            __syncthreads();

            const float* x = ring + (i & 1) * TILE_FLOATS + threadIdx.x * NC;

            float v[NC];
            #pragma unroll
            for (int c = 0; c < NC; c++) v[c] = x[c];
            const float xt = x[tgt];

            __syncthreads();                 // slot fully read -> refill ok
            if (i + STAGES < TPB)
                stage_tile(of, s, lt0 + i + STAGES, sb + (i & 1) * TILE_BYTES);
            else
                asm volatile("cp.async.commit_group;\n");

            float m = v[0];
            #pragma unroll
            for (int c = 1; c < NC; c++) m = fmaxf(m, v[c]);

            float sum = 0.f;
            #pragma unroll
            for (int c = 0; c < NC; c++) sum += __expf(v[c] - m);

            acc += __logf(sum) + m - xt;
        }
        asm volatile("cp.async.wait_group 0;\n" ::: "memory");

        // single block reduction at the end
        #pragma unroll
        for (int o = 16; o > 0; o >>= 1)
            acc += __shfl_down_sync(0xFFFFFFFFu, acc, o);
        const int wid = threadIdx.x >> 5;
        const int lid = threadIdx.x & 31;
        if (lid == 0) wred[wid] = acc;
        __syncthreads();
        if (threadIdx.x == 0) {
            float a = 0.f;
            #pragma unroll
            for (int w = 0; w < BLOCK / 32; w++) a += wred[w];
            g_fret_part[bid] = a;
        }
    } else {
        // ========== onset (softmax over batch), one string per block ==========
        __shared__ float colloss[OC];
        float* so  = ring;                   // [64 x 40]
        float* st_ = ring + NB * OC;
        const int ob   = bid - FRET_BLKS;    // 0..299, grouped by string
        const int col0 = ob * OC;            // global column (s*2000 + t0)

        for (int i = threadIdx.x; i < NB * OC; i += BLOCK) {
            int b = i / OC, c = i - b * OC;
            int gidx = b * COLS + col0 + c;
            so[i]  = oo[gidx];
            st_[i] = to[gidx];
        }
        __syncthreads();

        if (threadIdx.x < 4 * OC) {          // 160 threads = 5 FULL warps
            const int c = threadIdx.x >> 2;  // column 0..39
            const int q = threadIdx.x & 3;   // batch quarter

            float m = -3.402823466e+38f;
            #pragma unroll
            for (int i = 0; i < 16; i++)
                m = fmaxf(m, so[(q * 16 + i) * OC + c]);
            m = fmaxf(m, __shfl_xor_sync(0xFFFFFFFFu, m, 1));
            m = fmaxf(m, __shfl_xor_sync(0xFFFFFFFFu, m, 2));

            float sum = 0.f, ts = 0.f, txs = 0.f;
            #pragma unroll
            for (int i = 0; i < 16; i++) {
                float xv = so [(q * 16 + i) * OC + c];
                float tg = st_[(q * 16 + i) * OC + c];
                sum += __expf(xv - m);
                ts  += tg;
                txs += tg * xv;
            }
            sum += __shfl_xor_sync(0xFFFFFFFFu, sum, 1);
            sum += __shfl_xor_sync(0xFFFFFFFFu, sum, 2);
            ts  += __shfl_xor_sync(0xFFFFFFFFu, ts, 1);
            ts  += __shfl_xor_sync(0xFFFFFFFFu, ts, 2);
            txs += __shfl_xor_sync(0xFFFFFFFFu, txs, 1);
            txs += __shfl_xor_sync(0xFFFFFFFFu, txs, 2);

            if (q == 0)
                colloss[c] = (__logf(sum) + m) * ts - txs;
        }
        __syncthreads();

        // reduce the 40 column losses to one scalar (warp 0, full warp active)
        if (threadIdx.x < 32) {
            float a = (threadIdx.x < OC) ? colloss[threadIdx.x] : 0.f;
            if (threadIdx.x + 32 < OC) a += colloss[threadIdx.x + 32];
            #pragma unroll
            for (int o = 16; o > 0; o >>= 1)
                a += __shfl_down_sync(0xFFFFFFFFu, a, o);
            if (threadIdx.x == 0)
                g_onset_part[ob] = a;
        }
    }
}

// ---------------------------------------------------------------------------
// Final deterministic reduction over 1050 partials (L2-resident).
// Output (15 fp32): loss, fret_loss, onset_loss, fret_string[6], onset_string[6].
// ---------------------------------------------------------------------------
__global__ void final_kernel(float* __restrict__ out, int out_size)
{
    __shared__ float fs[NS], os_[NS];
    const int w   = threadIdx.x >> 5;
    const int lid = threadIdx.x & 31;

    if (w < NS) {
        float a = 0.f;
        for (int i = lid; i < BLKS_PER_S; i += 32)
            a += g_fret_part[w * BLKS_PER_S + i];
        #pragma unroll
        for (int o = 16; o > 0; o >>= 1)
            a += __shfl_down_sync(0xFFFFFFFFu, a, o);

        float b = 0.f;
        for (int i = lid; i < OBLKS_PER_S; i += 32)
            b += g_onset_part[w * OBLKS_PER_S + i];
        #pragma unroll
        for (int o = 16; o > 0; o >>= 1)
            b += __shfl_down_sync(0xFFFFFFFFu, b, o);

        if (lid == 0) {
            fs[w]  = a * (1.0f / NB);        // mean over batch
            os_[w] = b;
        }
    }
    __syncthreads();

    if (threadIdx.x == 0) {
        float fl = 0.f, ol = 0.f;
        #pragma unroll
        for (int s = 0; s < NS; s++) { fl += fs[s]; ol += os_[s]; }
        float loss = 0.5f * fl + 0.5f * ol;
        if (0 < out_size) out[0] = loss;
        if (1 < out_size) out[1] = fl;
        if (2 < out_size) out[2] = ol;
        #pragma unroll
        for (int s = 0; s < NS; s++) {
            if (3 + s < out_size) out[3 + s] = fs[s];
            if (9 + s < out_size) out[9 + s] = os_[s];
        }
    }
    for (int i = 15 + (int)threadIdx.x; i < out_size; i += (int)blockDim.x)
        out[i] = 0.f;
}

extern "C" void kernel_launch(void* const* d_in, const int* in_sizes, int n_in,
                              void* d_out, int out_size) {
    const float* output_fret  = (const float*)d_in[0];
    const int*   target_fret  = (const int*)  d_in[1];
    const float* output_onset = (const float*)d_in[2];
    const float* target_onset = (const float*)d_in[3];
    float* out = (float*)d_out;

    cudaFuncSetAttribute(fused_kernel,
                         cudaFuncAttributeMaxDynamicSharedMemorySize,
                         RING_BYTES);

    fused_kernel<<<GRID, BLOCK, RING_BYTES>>>(
        output_fret, target_fret, output_onset, target_onset);
    final_kernel<<<1, 192>>>(out, out_size);
}

// round 14
// speedup vs baseline: 1.6229x; 1.0101x over previous
#include <cuda_runtime.h>
#include <cuda_bf16.h>
#include <cstdint>

#define NB   64
#define NS   6
#define NT   2000
#define NC   25
#define BLOCK        256
#define TILE_ROWS    256
#define TILES_PER_S  500                   // 128000/256
#define TPB          4                     // tiles per fret block (same s)
#define BLKS_PER_S   (TILES_PER_S / TPB)   // 125
#define FRET_BLKS    (NS * BLKS_PER_S)     // 750
#define OC           40                    // onset cols per block; 4*OC=160 = 5 full warps
#define OBLKS_PER_S  (NT / OC)             // 50
#define ONSET_BLKS   (NS * OBLKS_PER_S)    // 300
#define GRID         (FRET_BLKS + ONSET_BLKS)  // 1050
#define STAGES       2
#define PLANE        (NT * NC)             // 50000
#define BSTRIDE      (NS * NT * NC)        // 300000
#define COLS         (NS * NT)             // 12000
#define TILE_FLOATS  (TILE_ROWS * NC)      // 6400
#define TILE_F4      (TILE_FLOATS / 4)     // 1600
#define TILE_BYTES   (TILE_FLOATS * 4)     // 25600
#define RING_BYTES   (STAGES * TILE_BYTES) // 51200

__device__ float g_fret_part[FRET_BLKS];   // per-block partial, grouped by s
__device__ float g_onset_part[ONSET_BLKS]; // per-block partial, grouped by s
__device__ int   g_count;                  // zero-init; reset by last block each run

__device__ __forceinline__ uint32_t s2u(const void* p) {
    uint32_t a;
    asm("{ .reg .u64 t; cvta.to.shared.u64 t, %1; cvt.u32.u64 %0, t; }"
        : "=r"(a) : "l"(p));
    return a;
}
__device__ __forceinline__ void cp16(uint32_t dst, const void* src) {
    asm volatile("cp.async.cg.shared.global [%0], [%1], 16;\n"
                 :: "r"(dst), "l"(src));
}

// Stage one 256-row tile: string s, local tile lt (0..499) -> smem slot.
__device__ __forceinline__ void stage_tile(const float* __restrict__ of,
                                           int s, int lt, uint32_t sbase) {
    const int p0 = lt * TILE_FLOATS;         // float offset within the s-plane
    #pragma unroll
    for (int j = 0; j < 7; j++) {
        int q = threadIdx.x + j * BLOCK;     // float4 index in tile
        if (q < TILE_F4) {
            int p = p0 + q * 4;
            int b = p / PLANE;               // constant across the float4
            const float* src = of + (p + b * (BSTRIDE - PLANE) + s * PLANE);
            cp16(sbase + q * 16, src);
        }
    }
    asm volatile("cp.async.commit_group;\n");
}

extern __shared__ float ring[];              // STAGES * TILE_FLOATS floats

__global__ __launch_bounds__(BLOCK) void fused_kernel(
    const float* __restrict__ of,    // [B,S,T,C]
    const int*   __restrict__ tf,    // [B,S,T]
    const float* __restrict__ oo,    // [B,S,T]
    const float* __restrict__ to,    // [B,S,T]
    float* __restrict__ out, int out_size)
{
    __shared__ int s_last;
    const int bid = blockIdx.x;

    if (bid < FRET_BLKS) {
        // ======================= fret CE =======================
        __shared__ float wred[BLOCK / 32];
        const int s   = bid / BLKS_PER_S;
        const int blk = bid - s * BLKS_PER_S;
        const int lt0 = blk * TPB;           // first local tile (0..499)
        const uint32_t sb = s2u(ring);

        stage_tile(of, s, lt0 + 0, sb);
        stage_tile(of, s, lt0 + 1, sb + TILE_BYTES);

        float acc = 0.f;                     // per-thread NLL accumulator

        #pragma unroll
        for (int i = 0; i < TPB; i++) {
            const int row = (lt0 + i) * TILE_ROWS + threadIdx.x;
            const int b   = row / NT;
            const int t   = row - b * NT;
            const int tgt = tf[(b * NS + s) * NT + t];  // LDG before the wait

            asm volatile("cp.async.wait_group %0;\n" :: "n"(STAGES - 1) : "memory");
            __syncthreads();

            const float* x = ring + (i & 1) * TILE_FLOATS + threadIdx.x * NC;

            float v[NC];
            #pragma unroll
            for (int c = 0; c < NC; c++) v[c] = x[c];
            const float xt = x[tgt];

            __syncthreads();                 // slot fully read -> refill ok
            if (i + STAGES < TPB)
                stage_tile(of, s, lt0 + i + STAGES, sb + (i & 1) * TILE_BYTES);
            else
                asm volatile("cp.async.commit_group;\n");

            float m = v[0];
            #pragma unroll
            for (int c = 1; c < NC; c++) m = fmaxf(m, v[c]);

            float sum = 0.f;
            #pragma unroll
            for (int c = 0; c < NC; c++) sum += __expf(v[c] - m);

            acc += __logf(sum) + m - xt;
        }
        asm volatile("cp.async.wait_group 0;\n" ::: "memory");

        // single block reduction at the end
        #pragma unroll
        for (int o = 16; o > 0; o >>= 1)
            acc += __shfl_down_sync(0xFFFFFFFFu, acc, o);
        const int wid = threadIdx.x >> 5;
        const int lid = threadIdx.x & 31;
        if (lid == 0) wred[wid] = acc;
        __syncthreads();
        if (threadIdx.x == 0) {
            float a = 0.f;
            #pragma unroll
            for (int w = 0; w < BLOCK / 32; w++) a += wred[w];
            g_fret_part[bid] = a;
        }
    } else {
        // ========== onset (softmax over batch), one string per block ==========
        __shared__ float colloss[OC];
        float* so  = ring;                   // [64 x 40]
        float* st_ = ring + NB * OC;
        const int ob   = bid - FRET_BLKS;    // 0..299, grouped by string
        const int col0 = ob * OC;            // global column (s*2000 + t0)

        for (int i = threadIdx.x; i < NB * OC; i += BLOCK) {
            int b = i / OC, c = i - b * OC;
            int gidx = b * COLS + col0 + c;
            so[i]  = oo[gidx];
            st_[i] = to[gidx];
        }
        __syncthreads();

        if (threadIdx.x < 4 * OC) {          // 160 threads = 5 FULL warps
            const int c = threadIdx.x >> 2;  // column 0..39
            const int q = threadIdx.x & 3;   // batch quarter

            float m = -3.402823466e+38f;
            #pragma unroll
            for (int i = 0; i < 16; i++)
                m = fmaxf(m, so[(q * 16 + i) * OC + c]);
            m = fmaxf(m, __shfl_xor_sync(0xFFFFFFFFu, m, 1));
            m = fmaxf(m, __shfl_xor_sync(0xFFFFFFFFu, m, 2));

            float sum = 0.f, ts = 0.f, txs = 0.f;
            #pragma unroll
            for (int i = 0; i < 16; i++) {
                float xv = so [(q * 16 + i) * OC + c];
                float tg = st_[(q * 16 + i) * OC + c];
                sum += __expf(xv - m);
                ts  += tg;
                txs += tg * xv;
            }
            sum += __shfl_xor_sync(0xFFFFFFFFu, sum, 1);
            sum += __shfl_xor_sync(0xFFFFFFFFu, sum, 2);
            ts  += __shfl_xor_sync(0xFFFFFFFFu, ts, 1);
            ts  += __shfl_xor_sync(0xFFFFFFFFu, ts, 2);
            txs += __shfl_xor_sync(0xFFFFFFFFu, txs, 1);
            txs += __shfl_xor_sync(0xFFFFFFFFu, txs, 2);

            if (q == 0)
                colloss[c] = (__logf(sum) + m) * ts - txs;
        }
        __syncthreads();

        // reduce the 40 column losses to one scalar (warp 0, full warp active)
        if (threadIdx.x < 32) {
            float a = (threadIdx.x < OC) ? colloss[threadIdx.x] : 0.f;
            if (threadIdx.x + 32 < OC) a += colloss[threadIdx.x + 32];  // cols 32..39
            #pragma unroll
            for (int o = 16; o > 0; o >>= 1)
                a += __shfl_down_sync(0xFFFFFFFFu, a, o);
            if (threadIdx.x == 0)
                g_onset_part[ob] = a;
        }
    }

    // ============= last-block deterministic final reduction =============
    __threadfence();                         // publish this block's partial
    __syncthreads();
    if (threadIdx.x == 0)
        s_last = (atomicAdd(&g_count, 1) == GRID - 1) ? 1 : 0;
    __syncthreads();
    if (!s_last) return;

    __threadfence();                         // acquire: see all partials
    if (threadIdx.x == 0) g_count = 0;       // reset for next graph replay

    __shared__ float fs[NS], os_[NS];
    const int w   = threadIdx.x >> 5;
    const int lid = threadIdx.x & 31;

    if (w < NS) {
        float a = 0.f;
        for (int i = lid; i < BLKS_PER_S; i += 32)
            a += g_fret_part[w * BLKS_PER_S + i];
        #pragma unroll
        for (int o = 16; o > 0; o >>= 1)
            a += __shfl_down_sync(0xFFFFFFFFu, a, o);

        float b = 0.f;
        for (int i = lid; i < OBLKS_PER_S; i += 32)
            b += g_onset_part[w * OBLKS_PER_S + i];
        #pragma unroll
        for (int o = 16; o > 0; o >>= 1)
            b += __shfl_down_sync(0xFFFFFFFFu, b, o);

        if (lid == 0) {
            fs[w]  = a * (1.0f / NB);        // mean over batch
            os_[w] = b;
        }
    }
    __syncthreads();

    if (threadIdx.x == 0) {
        float fl = 0.f, ol = 0.f;
        #pragma unroll
        for (int s = 0; s < NS; s++) { fl += fs[s]; ol += os_[s]; }
        float loss = 0.5f * fl + 0.5f * ol;
        if (0 < out_size) out[0] = loss;
        if (1 < out_size) out[1] = fl;
        if (2 < out_size) out[2] = ol;
        #pragma unroll
        for (int s = 0; s < NS; s++) {
            if (3 + s < out_size) out[3 + s] = fs[s];
            if (9 + s < out_size) out[9 + s] = os_[s];
        }
    }
    for (int i = 15 + (int)threadIdx.x; i < out_size; i += (int)blockDim.x)
        out[i] = 0.f;
}

extern "C" void kernel_launch(void* const* d_in, const int* in_sizes, int n_in,
                              void* d_out, int out_size) {
    const float* output_fret  = (const float*)d_in[0];
    const int*   target_fret  = (const int*)  d_in[1];
    const float* output_onset = (const float*)d_in[2];
    const float* target_onset = (const float*)d_in[3];
    float* out = (float*)d_out;

    cudaFuncSetAttribute(fused_kernel,
                         cudaFuncAttributeMaxDynamicSharedMemorySize,
                         RING_BYTES);

    fused_kernel<<<GRID, BLOCK, RING_BYTES>>>(
        output_fret, target_fret, output_onset, target_onset, out, out_size);
}